// round 2
// baseline (speedup 1.0000x reference)
#include <cuda_runtime.h>
#include <cuda_bf16.h>

// DNM_Linear: out[b,o] = relu(0.25 * sum_{m,i} relu(x[b,i]*W[o,m,i] - q[o,m,i]) - 0.05)
// x: [512,512] f32, W/q: [128,8,512] -> flat [1024,512] f32, out: [512,128] f32
//
// f32x2-packed along K: each 64-bit lane-pair holds even/odd-k partial terms of
// the SAME output, so x/W/q pairs load contiguously (no broadcasts).

#define IN_DIM  512
#define OUT_DIM 128
#define NEUR    1024
#define B_TOT   512
#define BT      64
#define NT      64
#define KC      64            // k per chunk
#define KK      (KC/2)        // 32 k-pairs per chunk
#define PITCH   132           // 2*64 + 4 floats (16B-aligned rows, bank stagger)
#define ARR     (KK*PITCH)    // floats per array per buffer
#define BUF     (3*ARR)       // x, w, -q
#define SMEM_BYTES (2*BUF*4)  // double buffered: 101,376 B

typedef unsigned long long u64;

__device__ __forceinline__ u64 fma2(u64 a, u64 b, u64 c) {
    u64 d; asm("fma.rn.f32x2 %0, %1, %2, %3;" : "=l"(d) : "l"(a), "l"(b), "l"(c)); return d;
}
__device__ __forceinline__ u64 add2(u64 a, u64 b) {
    u64 d; asm("add.rn.f32x2 %0, %1, %2;" : "=l"(d) : "l"(a), "l"(b)); return d;
}
__device__ __forceinline__ u64 relu2(u64 v) {
    float2 f = *reinterpret_cast<float2*>(&v);
    f.x = fmaxf(f.x, 0.f);
    f.y = fmaxf(f.y, 0.f);
    return *reinterpret_cast<u64*>(&f);
}

extern __shared__ float smem[];

__global__ __launch_bounds__(512, 1)
void dnm_kernel(const float* __restrict__ x,
                const float* __restrict__ W,
                const float* __restrict__ q,
                float* __restrict__ out)
{
    const int t  = threadIdx.x;
    const int n0 = blockIdx.x * NT;
    const int b0 = blockIdx.y * BT;

    // ---- global load mapping: 8 threads/row, float4 at kq and kq+32
    const int lrow = t >> 3;          // 0..63
    const int lk   = (t & 7) * 4;     // 0,4,...,28
    const float* xg = x + (size_t)(b0 + lrow) * IN_DIM + lk;
    const float* wg = W + (size_t)(n0 + lrow) * IN_DIM + lk;
    const float* qg = q + (size_t)(n0 + lrow) * IN_DIM + lk;

    // ---- compute mapping: 16(cols) x 32(rows) threads; 2 rows x 4 cols each
    const int tx = t & 15;            // cols tx*4 .. tx*4+3
    const int ty = t >> 4;            // rows ty*2, ty*2+1

    u64 acc[2][4];
#pragma unroll
    for (int r = 0; r < 2; r++)
#pragma unroll
        for (int j = 0; j < 4; j++) acc[r][j] = 0ull;

    float4 px[2], pw[2], pq[2];

    // prologue: load chunk 0
#pragma unroll
    for (int h = 0; h < 2; h++) {
        px[h] = *(const float4*)(xg + h * 32);
        pw[h] = *(const float4*)(wg + h * 32);
        pq[h] = *(const float4*)(qg + h * 32);
    }
    // store chunk 0 -> buffer 0  (k-pair-major: [kk][idx*2 + parity]); q negated
    {
        float* bx = smem;
        float* bw = smem + ARR;
        float* bq = smem + 2 * ARR;
#pragma unroll
        for (int h = 0; h < 2; h++) {
            const int kk0 = (lk >> 1) + h * 16;
            *(float2*)(bx + (kk0    ) * PITCH + lrow * 2) = make_float2(px[h].x,  px[h].y);
            *(float2*)(bx + (kk0 + 1) * PITCH + lrow * 2) = make_float2(px[h].z,  px[h].w);
            *(float2*)(bw + (kk0    ) * PITCH + lrow * 2) = make_float2(pw[h].x,  pw[h].y);
            *(float2*)(bw + (kk0 + 1) * PITCH + lrow * 2) = make_float2(pw[h].z,  pw[h].w);
            *(float2*)(bq + (kk0    ) * PITCH + lrow * 2) = make_float2(-pq[h].x, -pq[h].y);
            *(float2*)(bq + (kk0 + 1) * PITCH + lrow * 2) = make_float2(-pq[h].z, -pq[h].w);
        }
    }
    __syncthreads();

    for (int c = 0; c < IN_DIM / KC; c++) {
        const float* cb = smem + (c & 1) * BUF;
        const float* bx = cb + ty * 4;
        const float* bw = cb + ARR + tx * 8;
        const float* bq = cb + 2 * ARR + tx * 8;

        // prefetch next chunk from global (overlaps with compute)
        if (c < IN_DIM / KC - 1) {
            const int kn = (c + 1) * KC;
#pragma unroll
            for (int h = 0; h < 2; h++) {
                px[h] = *(const float4*)(xg + kn + h * 32);
                pw[h] = *(const float4*)(wg + kn + h * 32);
                pq[h] = *(const float4*)(qg + kn + h * 32);
            }
        }

        // ---- compute 32 k-pair steps
#pragma unroll 16
        for (int kk = 0; kk < KK; kk++) {
            float4 xv  = *(const float4*)(bx + kk * PITCH);       // rows ty*2, ty*2+1 (k-pairs)
            float4 wv0 = *(const float4*)(bw + kk * PITCH);       // cols tx*4+0, +1
            float4 wv1 = *(const float4*)(bw + kk * PITCH + 4);   // cols tx*4+2, +3
            float4 qv0 = *(const float4*)(bq + kk * PITCH);
            float4 qv1 = *(const float4*)(bq + kk * PITCH + 4);

            u64 ux[2] = { *(u64*)&xv.x, *(u64*)&xv.z };
            u64 uw[4] = { *(u64*)&wv0.x, *(u64*)&wv0.z, *(u64*)&wv1.x, *(u64*)&wv1.z };
            u64 uq[4] = { *(u64*)&qv0.x, *(u64*)&qv0.z, *(u64*)&qv1.x, *(u64*)&qv1.z };

#pragma unroll
            for (int r = 0; r < 2; r++)
#pragma unroll
                for (int j = 0; j < 4; j++)
                    acc[r][j] = add2(acc[r][j], relu2(fma2(ux[r], uw[j], uq[j])));
        }

        // ---- store prefetched chunk into the other buffer
        if (c < IN_DIM / KC - 1) {
            float* nb = smem + ((c + 1) & 1) * BUF;
            float* bx2 = nb;
            float* bw2 = nb + ARR;
            float* bq2 = nb + 2 * ARR;
#pragma unroll
            for (int h = 0; h < 2; h++) {
                const int kk0 = (lk >> 1) + h * 16;
                *(float2*)(bx2 + (kk0    ) * PITCH + lrow * 2) = make_float2(px[h].x,  px[h].y);
                *(float2*)(bx2 + (kk0 + 1) * PITCH + lrow * 2) = make_float2(px[h].z,  px[h].w);
                *(float2*)(bw2 + (kk0    ) * PITCH + lrow * 2) = make_float2(pw[h].x,  pw[h].y);
                *(float2*)(bw2 + (kk0 + 1) * PITCH + lrow * 2) = make_float2(pw[h].z,  pw[h].w);
                *(float2*)(bq2 + (kk0    ) * PITCH + lrow * 2) = make_float2(-pq[h].x, -pq[h].y);
                *(float2*)(bq2 + (kk0 + 1) * PITCH + lrow * 2) = make_float2(-pq[h].z, -pq[h].w);
            }
        }
        __syncthreads();
    }

    // ---- epilogue: fold k-parity lanes, then m=8 neurons -> one output
#pragma unroll
    for (int r = 0; r < 2; r++) {
        float s4 = 0.f;
#pragma unroll
        for (int j = 0; j < 4; j++) {
            float2 f = *reinterpret_cast<float2*>(&acc[r][j]);
            s4 += f.x + f.y;
        }
        float raw8 = s4 + __shfl_xor_sync(0xffffffffu, s4, 1);  // partner flips tx bit0
        if ((tx & 1) == 0) {
            int b = b0 + ty * 2 + r;
            int o = (n0 >> 3) + (tx >> 1);
            out[b * OUT_DIM + o] = fmaxf(0.25f * raw8 - 0.05f, 0.f);
        }
    }
}

extern "C" void kernel_launch(void* const* d_in, const int* in_sizes, int n_in,
                              void* d_out, int out_size)
{
    const float* x = (const float*)d_in[0];
    const float* W = (const float*)d_in[1];
    const float* q = (const float*)d_in[2];
    float* out = (float*)d_out;

    cudaFuncSetAttribute(dnm_kernel, cudaFuncAttributeMaxDynamicSharedMemorySize, SMEM_BYTES);

    dim3 grid(NEUR / NT, B_TOT / BT);   // 16 x 8 = 128 CTAs, 512 threads
    dnm_kernel<<<grid, 512, SMEM_BYTES>>>(x, W, q, out);
}

// round 3
// speedup vs baseline: 1.1747x; 1.1747x over previous
#include <cuda_runtime.h>
#include <cuda_bf16.h>

// DNM_Linear: out[b,o] = relu(0.25 * sum_{m,i} relu(x[b,i]*W[o,m,i] - q[o,m,i]) - 0.05)
// x: [512,512] f32; W,q: [128,8,512] -> flat [1024,512] f32; out: [512,128] f32
//
// 128 thr/CTA, tile 64(batch)x64(neuron), thread-tile 8 rows x 4 cols, f32x2 packed
// along K. Crossbar-lean: 2 B/elem; fma-pipe: 1 packed instr/elem.

#define IN_DIM   512
#define OUT_DIM  128
#define NEUR     1024
#define B_TOT    512
#define KC       32          // k per chunk
#define KKC      16          // k-pairs per chunk
#define ROWF     128         // floats per kk-row (64 entity-pairs)
#define ARR      (KKC*ROWF)  // 2048 floats per array
#define BUF      (3*ARR)     // x, w, -q
#define SMEM_BYTES (2*BUF*4) // 49152 B

typedef unsigned long long u64;

__device__ __forceinline__ u64 fma2(u64 a, u64 b, u64 c) {
    u64 d; asm("fma.rn.f32x2 %0, %1, %2, %3;" : "=l"(d) : "l"(a), "l"(b), "l"(c)); return d;
}
__device__ __forceinline__ u64 add2(u64 a, u64 b) {
    u64 d; asm("add.rn.f32x2 %0, %1, %2;" : "=l"(d) : "l"(a), "l"(b)); return d;
}
__device__ __forceinline__ u64 relu2(u64 v) {
    float2 f = *reinterpret_cast<float2*>(&v);
    f.x = fmaxf(f.x, 0.f);
    f.y = fmaxf(f.y, 0.f);
    return *reinterpret_cast<u64*>(&f);
}

extern __shared__ float smem[];

__global__ __launch_bounds__(128, 1)
void dnm_kernel(const float* __restrict__ x,
                const float* __restrict__ W,
                const float* __restrict__ q,
                float* __restrict__ out)
{
    const int t  = threadIdx.x;
    const int n0 = blockIdx.x * 64;
    const int b0 = blockIdx.y * 64;

    // compute mapping: 16 cols-groups x 8 row-groups
    const int tx = t & 15;     // neuron cols tx*4 .. tx*4+3
    const int ty = t >> 4;     // batch rows  ty*8 .. ty*8+7

    // global load mapping: 2 threads per entity row, 16 k each (4 float4)
    const int e  = t >> 1;         // entity 0..63
    const int kh = (t & 1) * 16;   // k half 0 or 16

    const float* xg = x + (size_t)(b0 + e) * IN_DIM + kh;
    const float* wg = W + (size_t)(n0 + e) * IN_DIM + kh;
    const float* qg = q + (size_t)(n0 + e) * IN_DIM + kh;

    u64 acc[8][4];
#pragma unroll
    for (int r = 0; r < 8; r++)
#pragma unroll
        for (int j = 0; j < 4; j++) acc[r][j] = 0ull;

    float4 px[4], pw[4], pq[4];

    // ---- prologue: load + store chunk 0
#pragma unroll
    for (int j = 0; j < 4; j++) {
        px[j] = *(const float4*)(xg + j * 4);
        pw[j] = *(const float4*)(wg + j * 4);
        pq[j] = *(const float4*)(qg + j * 4);
    }
    {
        float* bx = smem;
        float* bw = smem + ARR;
        float* bq = smem + 2 * ARR;
#pragma unroll
        for (int j = 0; j < 4; j++) {
            const int kk0 = (kh + j * 4) >> 1;
            *(float2*)(bx + (kk0    ) * ROWF + e * 2) = make_float2(px[j].x,  px[j].y);
            *(float2*)(bx + (kk0 + 1) * ROWF + e * 2) = make_float2(px[j].z,  px[j].w);
            *(float2*)(bw + (kk0    ) * ROWF + e * 2) = make_float2(pw[j].x,  pw[j].y);
            *(float2*)(bw + (kk0 + 1) * ROWF + e * 2) = make_float2(pw[j].z,  pw[j].w);
            *(float2*)(bq + (kk0    ) * ROWF + e * 2) = make_float2(-pq[j].x, -pq[j].y);
            *(float2*)(bq + (kk0 + 1) * ROWF + e * 2) = make_float2(-pq[j].z, -pq[j].w);
        }
    }
    __syncthreads();

    const int NCHUNK = IN_DIM / KC;  // 16
    for (int c = 0; c < NCHUNK; c++) {
        // prefetch next chunk (overlaps compute)
        if (c < NCHUNK - 1) {
            const int kn = (c + 1) * KC;
#pragma unroll
            for (int j = 0; j < 4; j++) {
                px[j] = *(const float4*)(xg + kn + j * 4);
                pw[j] = *(const float4*)(wg + kn + j * 4);
                pq[j] = *(const float4*)(qg + kn + j * 4);
            }
        }

        const float* cb = smem + (c & 1) * BUF;
        const float* bx = cb + ty * 16;
        const float* bw = cb + ARR + tx * 8;
        const float* bq = cb + 2 * ARR + tx * 8;

#pragma unroll 8
        for (int kk = 0; kk < KKC; kk++) {
            float4 xv0 = *(const float4*)(bx + kk * ROWF);        // row pairs 0-1
            float4 xv1 = *(const float4*)(bx + kk * ROWF + 4);    // 2-3
            float4 xv2 = *(const float4*)(bx + kk * ROWF + 8);    // 4-5
            float4 xv3 = *(const float4*)(bx + kk * ROWF + 12);   // 6-7
            float4 wv0 = *(const float4*)(bw + kk * ROWF);        // col pairs 0-1
            float4 wv1 = *(const float4*)(bw + kk * ROWF + 4);    // 2-3
            float4 qv0 = *(const float4*)(bq + kk * ROWF);
            float4 qv1 = *(const float4*)(bq + kk * ROWF + 4);

            u64 ux[8] = { *(u64*)&xv0.x, *(u64*)&xv0.z,
                          *(u64*)&xv1.x, *(u64*)&xv1.z,
                          *(u64*)&xv2.x, *(u64*)&xv2.z,
                          *(u64*)&xv3.x, *(u64*)&xv3.z };
            u64 uw[4] = { *(u64*)&wv0.x, *(u64*)&wv0.z,
                          *(u64*)&wv1.x, *(u64*)&wv1.z };
            u64 uq[4] = { *(u64*)&qv0.x, *(u64*)&qv0.z,
                          *(u64*)&qv1.x, *(u64*)&qv1.z };

#pragma unroll
            for (int r = 0; r < 8; r++)
#pragma unroll
                for (int j = 0; j < 4; j++)
                    acc[r][j] = add2(acc[r][j], relu2(fma2(ux[r], uw[j], uq[j])));
        }

        // store prefetched chunk into the other buffer
        if (c < NCHUNK - 1) {
            float* nb = smem + ((c + 1) & 1) * BUF;
            float* bx2 = nb;
            float* bw2 = nb + ARR;
            float* bq2 = nb + 2 * ARR;
#pragma unroll
            for (int j = 0; j < 4; j++) {
                const int kk0 = (kh + j * 4) >> 1;
                *(float2*)(bx2 + (kk0    ) * ROWF + e * 2) = make_float2(px[j].x,  px[j].y);
                *(float2*)(bx2 + (kk0 + 1) * ROWF + e * 2) = make_float2(px[j].z,  px[j].w);
                *(float2*)(bw2 + (kk0    ) * ROWF + e * 2) = make_float2(pw[j].x,  pw[j].y);
                *(float2*)(bw2 + (kk0 + 1) * ROWF + e * 2) = make_float2(pw[j].z,  pw[j].w);
                *(float2*)(bq2 + (kk0    ) * ROWF + e * 2) = make_float2(-pq[j].x, -pq[j].y);
                *(float2*)(bq2 + (kk0 + 1) * ROWF + e * 2) = make_float2(-pq[j].z, -pq[j].w);
            }
        }
        __syncthreads();
    }

    // ---- epilogue: fold k-parity, then m=8 neuron-cols via shfl pair
#pragma unroll
    for (int r = 0; r < 8; r++) {
        float s = 0.f;
#pragma unroll
        for (int j = 0; j < 4; j++) {
            float2 f = *reinterpret_cast<float2*>(&acc[r][j]);
            s += f.x + f.y;
        }
        float raw8 = s + __shfl_xor_sync(0xffffffffu, s, 1);  // partner flips tx bit0
        if ((tx & 1) == 0) {
            int b = b0 + ty * 8 + r;
            int o = (n0 >> 3) + (tx >> 1);
            out[b * OUT_DIM + o] = fmaxf(0.25f * raw8 - 0.05f, 0.f);
        }
    }
}

extern "C" void kernel_launch(void* const* d_in, const int* in_sizes, int n_in,
                              void* d_out, int out_size)
{
    const float* x = (const float*)d_in[0];
    const float* W = (const float*)d_in[1];
    const float* q = (const float*)d_in[2];
    float* out = (float*)d_out;

    cudaFuncSetAttribute(dnm_kernel, cudaFuncAttributeMaxDynamicSharedMemorySize, SMEM_BYTES);

    dim3 grid(NEUR / 64, B_TOT / 64);   // 16 x 8 = 128 CTAs, 128 threads each
    dnm_kernel<<<grid, 128, SMEM_BYTES>>>(x, W, q, out);
}

// round 4
// speedup vs baseline: 1.4496x; 1.2340x over previous
#include <cuda_runtime.h>
#include <cuda_bf16.h>

// DNM_Linear: out[b,o] = relu(0.25 * sum_{m,i} relu(x[b,i]*W[o,m,i] - q[o,m,i]) - 0.05)
// x: [512,512] f32; W,q: [128,8,512] -> flat [1024,512] f32; out: [512,128] f32
//
// 256 thr/CTA (2 warps/SMSP), tile 64x64, thread-tile 4x4, f32x2 packed along K.

#define IN_DIM   512
#define OUT_DIM  128
#define NEUR     1024
#define B_TOT    512
#define KC       32          // k per chunk
#define KKC      16          // k-pairs per chunk
#define ROWF     128         // floats per kk-row (64 entities x 2)
#define ARR      (KKC*ROWF)  // 2048 floats
#define BUF      (3*ARR)     // x, w, -q
#define SMEM_BYTES (2*BUF*4) // 49152 B

typedef unsigned long long u64;

__device__ __forceinline__ u64 fma2(u64 a, u64 b, u64 c) {
    u64 d; asm("fma.rn.f32x2 %0, %1, %2, %3;" : "=l"(d) : "l"(a), "l"(b), "l"(c)); return d;
}
__device__ __forceinline__ u64 add2(u64 a, u64 b) {
    u64 d; asm("add.rn.f32x2 %0, %1, %2;" : "=l"(d) : "l"(a), "l"(b)); return d;
}
__device__ __forceinline__ u64 relu2(u64 v) {
    float2 f = *reinterpret_cast<float2*>(&v);
    f.x = fmaxf(f.x, 0.f);
    f.y = fmaxf(f.y, 0.f);
    return *reinterpret_cast<u64*>(&f);
}

extern __shared__ float smem[];

__global__ __launch_bounds__(256, 1)
void dnm_kernel(const float* __restrict__ x,
                const float* __restrict__ W,
                const float* __restrict__ q,
                float* __restrict__ out)
{
    const int t  = threadIdx.x;
    const int n0 = blockIdx.x * 64;
    const int b0 = blockIdx.y * 64;

    // compute mapping: 16 col-groups x 16 row-groups; 4 rows x 4 cols per thread
    const int tx = t & 15;     // neuron cols tx*4 .. tx*4+3
    const int ty = t >> 4;     // batch rows  ty*4 .. ty*4+3

    // global load mapping (coalesced): 4 threads per entity row, 8 k each
    const int e  = t >> 2;          // entity 0..63
    const int kq = (t & 3) * 8;     // 0,8,16,24

    const float* xg = x + (size_t)(b0 + e) * IN_DIM + kq;
    const float* wg = W + (size_t)(n0 + e) * IN_DIM + kq;
    const float* qg = q + (size_t)(n0 + e) * IN_DIM + kq;

    u64 acc[4][4];
#pragma unroll
    for (int r = 0; r < 4; r++)
#pragma unroll
        for (int j = 0; j < 4; j++) acc[r][j] = 0ull;

    float4 px[2], pw[2], pq[2];

    // ---- prologue: load + store chunk 0
#pragma unroll
    for (int j = 0; j < 2; j++) {
        px[j] = *(const float4*)(xg + j * 4);
        pw[j] = *(const float4*)(wg + j * 4);
        pq[j] = *(const float4*)(qg + j * 4);
    }
    {
        float* bx = smem;
        float* bw = smem + ARR;
        float* bq = smem + 2 * ARR;
#pragma unroll
        for (int j = 0; j < 2; j++) {
            const int kk0 = (kq >> 1) + j * 2;
            *(float2*)(bx + (kk0    ) * ROWF + e * 2) = make_float2(px[j].x,  px[j].y);
            *(float2*)(bx + (kk0 + 1) * ROWF + e * 2) = make_float2(px[j].z,  px[j].w);
            *(float2*)(bw + (kk0    ) * ROWF + e * 2) = make_float2(pw[j].x,  pw[j].y);
            *(float2*)(bw + (kk0 + 1) * ROWF + e * 2) = make_float2(pw[j].z,  pw[j].w);
            *(float2*)(bq + (kk0    ) * ROWF + e * 2) = make_float2(-pq[j].x, -pq[j].y);
            *(float2*)(bq + (kk0 + 1) * ROWF + e * 2) = make_float2(-pq[j].z, -pq[j].w);
        }
    }
    __syncthreads();

    const int NCHUNK = IN_DIM / KC;  // 16
    for (int c = 0; c < NCHUNK; c++) {
        // prefetch next chunk from global (overlaps compute)
        if (c < NCHUNK - 1) {
            const int kn = (c + 1) * KC;
#pragma unroll
            for (int j = 0; j < 2; j++) {
                px[j] = *(const float4*)(xg + kn + j * 4);
                pw[j] = *(const float4*)(wg + kn + j * 4);
                pq[j] = *(const float4*)(qg + kn + j * 4);
            }
        }

        const float* cb = smem + (c & 1) * BUF;
        const float* bx = cb + ty * 8;
        const float* bw = cb + ARR + tx * 8;
        const float* bq = cb + 2 * ARR + tx * 8;

#pragma unroll
        for (int kk = 0; kk < KKC; kk++) {
            float4 xv0 = *(const float4*)(bx + kk * ROWF);      // rows 0-1 (k-pairs)
            float4 xv1 = *(const float4*)(bx + kk * ROWF + 4);  // rows 2-3
            float4 wv0 = *(const float4*)(bw + kk * ROWF);      // cols 0-1
            float4 wv1 = *(const float4*)(bw + kk * ROWF + 4);  // cols 2-3
            float4 qv0 = *(const float4*)(bq + kk * ROWF);
            float4 qv1 = *(const float4*)(bq + kk * ROWF + 4);

            u64 ux[4] = { *(u64*)&xv0.x, *(u64*)&xv0.z, *(u64*)&xv1.x, *(u64*)&xv1.z };
            u64 uw[4] = { *(u64*)&wv0.x, *(u64*)&wv0.z, *(u64*)&wv1.x, *(u64*)&wv1.z };
            u64 uq[4] = { *(u64*)&qv0.x, *(u64*)&qv0.z, *(u64*)&qv1.x, *(u64*)&qv1.z };

#pragma unroll
            for (int r = 0; r < 4; r++)
#pragma unroll
                for (int j = 0; j < 4; j++)
                    acc[r][j] = add2(acc[r][j], relu2(fma2(ux[r], uw[j], uq[j])));
        }

        // store prefetched chunk into the other buffer
        if (c < NCHUNK - 1) {
            float* nb = smem + ((c + 1) & 1) * BUF;
            float* bx2 = nb;
            float* bw2 = nb + ARR;
            float* bq2 = nb + 2 * ARR;
#pragma unroll
            for (int j = 0; j < 2; j++) {
                const int kk0 = (kq >> 1) + j * 2;
                *(float2*)(bx2 + (kk0    ) * ROWF + e * 2) = make_float2(px[j].x,  px[j].y);
                *(float2*)(bx2 + (kk0 + 1) * ROWF + e * 2) = make_float2(px[j].z,  px[j].w);
                *(float2*)(bw2 + (kk0    ) * ROWF + e * 2) = make_float2(pw[j].x,  pw[j].y);
                *(float2*)(bw2 + (kk0 + 1) * ROWF + e * 2) = make_float2(pw[j].z,  pw[j].w);
                *(float2*)(bq2 + (kk0    ) * ROWF + e * 2) = make_float2(-pq[j].x, -pq[j].y);
                *(float2*)(bq2 + (kk0 + 1) * ROWF + e * 2) = make_float2(-pq[j].z, -pq[j].w);
            }
        }
        __syncthreads();
    }

    // ---- epilogue: fold k-parity, then m=8 neuron-cols via shfl pair
#pragma unroll
    for (int r = 0; r < 4; r++) {
        float s = 0.f;
#pragma unroll
        for (int j = 0; j < 4; j++) {
            float2 f = *reinterpret_cast<float2*>(&acc[r][j]);
            s += f.x + f.y;
        }
        float raw8 = s + __shfl_xor_sync(0xffffffffu, s, 1);  // partner flips tx bit0
        if ((tx & 1) == 0) {
            int b = b0 + ty * 4 + r;
            int o = (n0 >> 3) + (tx >> 1);
            out[b * OUT_DIM + o] = fmaxf(0.25f * raw8 - 0.05f, 0.f);
        }
    }
}

extern "C" void kernel_launch(void* const* d_in, const int* in_sizes, int n_in,
                              void* d_out, int out_size)
{
    const float* x = (const float*)d_in[0];
    const float* W = (const float*)d_in[1];
    const float* q = (const float*)d_in[2];
    float* out = (float*)d_out;

    cudaFuncSetAttribute(dnm_kernel, cudaFuncAttributeMaxDynamicSharedMemorySize, SMEM_BYTES);

    dim3 grid(NEUR / 64, B_TOT / 64);   // 16 x 8 = 128 CTAs, 256 threads each
    dnm_kernel<<<grid, 256, SMEM_BYTES>>>(x, W, q, out);
}

// round 5
// speedup vs baseline: 2.0915x; 1.4427x over previous
#include <cuda_runtime.h>
#include <cuda_bf16.h>

// DNM_Linear: out[b,o] = relu(0.25 * sum_{m,i} relu(x[b,i]*W[o,m,i] - q[o,m,i]) - 0.05)
// x: [512,512] f32; W,q: [128,8,512] -> flat [1024,512] f32; out: [512,128] f32
//
// 256 thr/CTA, tile 64x64. Warp = 16 tx-lanes x 2 ty-lanes; ty splits K parity
// (zero w/q smem duplication), thread tile 8 rows x 4 cols (cols split 2+2 for
// conflict-free 16B-stride LDS.128). f32x2 packed along K.

#define IN_DIM   512
#define OUT_DIM  128
#define NEUR     1024
#define B_TOT    512
#define KC       32          // k per chunk
#define KKC      16          // k-pairs per chunk
#define NMAC     8           // macro steps per chunk (2 kk each)
#define ROWF     128         // floats per kk-row (64 entities x 2)
#define ARR      (KKC*ROWF)  // 2048 floats
#define BUF      (3*ARR)     // x, w, -q
#define SMEM_BYTES (2*BUF*4) // 49152 B

typedef unsigned long long u64;

__device__ __forceinline__ u64 fma2(u64 a, u64 b, u64 c) {
    u64 d; asm("fma.rn.f32x2 %0, %1, %2, %3;" : "=l"(d) : "l"(a), "l"(b), "l"(c)); return d;
}
__device__ __forceinline__ u64 add2(u64 a, u64 b) {
    u64 d; asm("add.rn.f32x2 %0, %1, %2;" : "=l"(d) : "l"(a), "l"(b)); return d;
}
__device__ __forceinline__ u64 relu2(u64 v) {
    float2 f = *reinterpret_cast<float2*>(&v);
    f.x = fmaxf(f.x, 0.f);
    f.y = fmaxf(f.y, 0.f);
    return *reinterpret_cast<u64*>(&f);
}

extern __shared__ float smem[];

__global__ __launch_bounds__(256, 1)
void dnm_kernel(const float* __restrict__ x,
                const float* __restrict__ W,
                const float* __restrict__ q,
                float* __restrict__ out)
{
    const int t    = threadIdx.x;
    const int lane = t & 31;
    const int wid  = t >> 5;          // warp 0..7 -> rows wid*8 .. wid*8+7
    const int tx   = lane & 15;       // col groups
    const int ty   = lane >> 4;       // k parity within macro step
    const int n0   = blockIdx.x * 64;
    const int b0   = blockIdx.y * 64;

    // global load mapping (same as before): 4 threads per entity row, 8 k each
    const int e  = t >> 2;
    const int kq = (t & 3) * 8;
    const float* xg = x + (size_t)(b0 + e) * IN_DIM + kq;
    const float* wg = W + (size_t)(n0 + e) * IN_DIM + kq;
    const float* qg = q + (size_t)(n0 + e) * IN_DIM + kq;

    // acc[r][j]: rows wid*8+r; cols j=0,1 -> {2tx,2tx+1}; j=2,3 -> {32+2tx,33+2tx}
    u64 acc[8][4];
#pragma unroll
    for (int r = 0; r < 8; r++)
#pragma unroll
        for (int j = 0; j < 4; j++) acc[r][j] = 0ull;

    float4 px[2], pw[2], pq[2];

    // ---- prologue: load + store chunk 0
#pragma unroll
    for (int j = 0; j < 2; j++) {
        px[j] = *(const float4*)(xg + j * 4);
        pw[j] = *(const float4*)(wg + j * 4);
        pq[j] = *(const float4*)(qg + j * 4);
    }
    {
        float* bx = smem;
        float* bw = smem + ARR;
        float* bq = smem + 2 * ARR;
#pragma unroll
        for (int j = 0; j < 2; j++) {
            const int kk0 = (kq >> 1) + j * 2;
            *(float2*)(bx + (kk0    ) * ROWF + e * 2) = make_float2(px[j].x,  px[j].y);
            *(float2*)(bx + (kk0 + 1) * ROWF + e * 2) = make_float2(px[j].z,  px[j].w);
            *(float2*)(bw + (kk0    ) * ROWF + e * 2) = make_float2(pw[j].x,  pw[j].y);
            *(float2*)(bw + (kk0 + 1) * ROWF + e * 2) = make_float2(pw[j].z,  pw[j].w);
            *(float2*)(bq + (kk0    ) * ROWF + e * 2) = make_float2(-pq[j].x, -pq[j].y);
            *(float2*)(bq + (kk0 + 1) * ROWF + e * 2) = make_float2(-pq[j].z, -pq[j].w);
        }
    }
    __syncthreads();

    const int NCHUNK = IN_DIM / KC;  // 16
    for (int c = 0; c < NCHUNK; c++) {
        // prefetch next chunk (overlaps compute)
        if (c < NCHUNK - 1) {
            const int kn = (c + 1) * KC;
#pragma unroll
            for (int j = 0; j < 2; j++) {
                px[j] = *(const float4*)(xg + kn + j * 4);
                pw[j] = *(const float4*)(wg + kn + j * 4);
                pq[j] = *(const float4*)(qg + kn + j * 4);
            }
        }

        const float* cb = smem + (c & 1) * BUF;
        // per-thread bases; ty selects the kk within each macro pair
        const float* bx = cb + ty * ROWF + wid * 16;            // x granules 4w..4w+3
        const float* bw = cb + ARR + ty * ROWF + tx * 4;        // w granules tx, 16+tx
        const float* bq = cb + 2 * ARR + ty * ROWF + tx * 4;

#pragma unroll
        for (int m = 0; m < NMAC; m++) {
            const int off = m * (2 * ROWF);
            // x: 8 rows (4 granules), this thread's kk parity
            float4 xv0 = *(const float4*)(bx + off);
            float4 xv1 = *(const float4*)(bx + off + 4);
            float4 xv2 = *(const float4*)(bx + off + 8);
            float4 xv3 = *(const float4*)(bx + off + 12);
            // w/q: granule tx (cols 2tx,2tx+1) and granule 16+tx (cols 32+2tx,33+2tx)
            float4 wv0 = *(const float4*)(bw + off);
            float4 wv1 = *(const float4*)(bw + off + 64);
            float4 qv0 = *(const float4*)(bq + off);
            float4 qv1 = *(const float4*)(bq + off + 64);

            u64 ux[8] = { *(u64*)&xv0.x, *(u64*)&xv0.z,
                          *(u64*)&xv1.x, *(u64*)&xv1.z,
                          *(u64*)&xv2.x, *(u64*)&xv2.z,
                          *(u64*)&xv3.x, *(u64*)&xv3.z };
            u64 uw[4] = { *(u64*)&wv0.x, *(u64*)&wv0.z,
                          *(u64*)&wv1.x, *(u64*)&wv1.z };
            u64 uq[4] = { *(u64*)&qv0.x, *(u64*)&qv0.z,
                          *(u64*)&qv1.x, *(u64*)&qv1.z };

#pragma unroll
            for (int r = 0; r < 8; r++)
#pragma unroll
                for (int j = 0; j < 4; j++)
                    acc[r][j] = add2(acc[r][j], relu2(fma2(ux[r], uw[j], uq[j])));
        }

        // store prefetched chunk into the other buffer
        if (c < NCHUNK - 1) {
            float* nb = smem + ((c + 1) & 1) * BUF;
            float* bx2 = nb;
            float* bw2 = nb + ARR;
            float* bq2 = nb + 2 * ARR;
#pragma unroll
            for (int j = 0; j < 2; j++) {
                const int kk0 = (kq >> 1) + j * 2;
                *(float2*)(bx2 + (kk0    ) * ROWF + e * 2) = make_float2(px[j].x,  px[j].y);
                *(float2*)(bx2 + (kk0 + 1) * ROWF + e * 2) = make_float2(px[j].z,  px[j].w);
                *(float2*)(bw2 + (kk0    ) * ROWF + e * 2) = make_float2(pw[j].x,  pw[j].y);
                *(float2*)(bw2 + (kk0 + 1) * ROWF + e * 2) = make_float2(pw[j].z,  pw[j].w);
                *(float2*)(bq2 + (kk0    ) * ROWF + e * 2) = make_float2(-pq[j].x, -pq[j].y);
                *(float2*)(bq2 + (kk0 + 1) * ROWF + e * 2) = make_float2(-pq[j].z, -pq[j].w);
            }
        }
        __syncthreads();
    }

    // ---- epilogue: fold k-parity (xor16), then 8-neuron groups (xor1, xor2)
    const unsigned FULL = 0xffffffffu;
#pragma unroll
    for (int r = 0; r < 8; r++) {
        float2 a0 = *reinterpret_cast<float2*>(&acc[r][0]);
        float2 a1 = *reinterpret_cast<float2*>(&acc[r][1]);
        float2 a2 = *reinterpret_cast<float2*>(&acc[r][2]);
        float2 a3 = *reinterpret_cast<float2*>(&acc[r][3]);
        float sA = a0.x + a0.y + a1.x + a1.y;   // cols 2tx, 2tx+1
        float sB = a2.x + a2.y + a3.x + a3.y;   // cols 32+2tx, 33+2tx

        sA += __shfl_xor_sync(FULL, sA, 16);    // fold k parity
        sB += __shfl_xor_sync(FULL, sB, 16);
        sA += __shfl_xor_sync(FULL, sA, 1);     // fold 4 lanes = 8 neurons
        sB += __shfl_xor_sync(FULL, sB, 1);
        sA += __shfl_xor_sync(FULL, sA, 2);
        sB += __shfl_xor_sync(FULL, sB, 2);

        if ((lane & 19) == 0) {                 // ty==0 && (tx&3)==0
            const int b  = b0 + wid * 8 + r;
            const int g  = tx >> 2;             // 0..3
            const int ob = n0 >> 3;
            out[b * OUT_DIM + ob + g]     = fmaxf(0.25f * sA - 0.05f, 0.f);
            out[b * OUT_DIM + ob + 4 + g] = fmaxf(0.25f * sB - 0.05f, 0.f);
        }
    }
}

extern "C" void kernel_launch(void* const* d_in, const int* in_sizes, int n_in,
                              void* d_out, int out_size)
{
    const float* x = (const float*)d_in[0];
    const float* W = (const float*)d_in[1];
    const float* q = (const float*)d_in[2];
    float* out = (float*)d_out;

    cudaFuncSetAttribute(dnm_kernel, cudaFuncAttributeMaxDynamicSharedMemorySize, SMEM_BYTES);

    dim3 grid(NEUR / 64, B_TOT / 64);   // 16 x 8 = 128 CTAs, 256 threads each
    dnm_kernel<<<grid, 256, SMEM_BYTES>>>(x, W, q, out);
}